// round 9
// baseline (speedup 1.0000x reference)
#include <cuda_runtime.h>
#include <cstdint>
#include <math.h>

// Problem constants
#define TT 512
#define BB 8
#define DD 512
#define NN 64

// Scratch (allocation-free rule: __device__ globals)
__device__ float g_k[TT * BB * DD];
__device__ float g_q[TT * BB * DD];
__device__ float g_wx[TT * BB * NN];     // W_x @ x + b  (bias folded)
__device__ float g_alpha[TT * BB * NN];  // sigmoid(W_alpha @ x + b_alpha)

// ============================================================================
// Kernel 1: fused projection GEMM
//   C[r, j] = sum_d x[r, d] * Wcat[j, d],   r = t*B+b  (M=4096, K=512)
//   cols 0..511   -> k_all
//   cols 512..1023-> q_all
//   cols 1024..1087-> wx_all (+ b)
//   cols 1088..1151-> alpha_all (sigmoid(. + b_alpha))
// ============================================================================
#define PM 4096
#define PK 512
#define PN 1152
#define TBM 128
#define TBN 128
#define TBK 16

__global__ __launch_bounds__(256) void proj_kernel(
    const float* __restrict__ x,
    const float* __restrict__ Wk, const float* __restrict__ Wq,
    const float* __restrict__ Wx, const float* __restrict__ Wa,
    const float* __restrict__ bvec, const float* __restrict__ ba)
{
    __shared__ float As[TBK][TBM + 4];
    __shared__ float Bs[TBK][TBN + 4];

    const int tid = threadIdx.x;
    const int tx = tid & 15;
    const int ty = tid >> 4;
    const int m0 = blockIdx.x * TBM;
    const int n0 = blockIdx.y * TBN;

    const int kq = tid & 3;      // which float4 along k
    const int r0 = tid >> 2;     // 0..63 (row/col within tile, +64 for second)

    // B row pointers (weights are [out, d] row-major, d contiguous -> NT GEMM)
    const float* wr0p;
    const float* wr1p;
    {
        int jg = n0 + r0;
        wr0p = (jg < 512) ? Wk + (size_t)jg * 512
             : (jg < 1024) ? Wq + (size_t)(jg - 512) * 512
             : (jg < 1088) ? Wx + (size_t)(jg - 1024) * 512
                           : Wa + (size_t)(jg - 1088) * 512;
        jg = n0 + r0 + 64;
        wr1p = (jg < 512) ? Wk + (size_t)jg * 512
             : (jg < 1024) ? Wq + (size_t)(jg - 512) * 512
             : (jg < 1088) ? Wx + (size_t)(jg - 1024) * 512
                           : Wa + (size_t)(jg - 1088) * 512;
    }
    const float* xr0 = x + (size_t)(m0 + r0) * PK;
    const float* xr1 = x + (size_t)(m0 + r0 + 64) * PK;

    float acc[8][8];
#pragma unroll
    for (int i = 0; i < 8; i++)
#pragma unroll
        for (int j = 0; j < 8; j++) acc[i][j] = 0.0f;

    for (int kt = 0; kt < PK; kt += TBK) {
        float4 a0 = *(const float4*)(xr0 + kt + kq * 4);
        float4 a1 = *(const float4*)(xr1 + kt + kq * 4);
        float4 b0 = *(const float4*)(wr0p + kt + kq * 4);
        float4 b1 = *(const float4*)(wr1p + kt + kq * 4);

        As[kq * 4 + 0][r0] = a0.x; As[kq * 4 + 1][r0] = a0.y;
        As[kq * 4 + 2][r0] = a0.z; As[kq * 4 + 3][r0] = a0.w;
        As[kq * 4 + 0][r0 + 64] = a1.x; As[kq * 4 + 1][r0 + 64] = a1.y;
        As[kq * 4 + 2][r0 + 64] = a1.z; As[kq * 4 + 3][r0 + 64] = a1.w;

        Bs[kq * 4 + 0][r0] = b0.x; Bs[kq * 4 + 1][r0] = b0.y;
        Bs[kq * 4 + 2][r0] = b0.z; Bs[kq * 4 + 3][r0] = b0.w;
        Bs[kq * 4 + 0][r0 + 64] = b1.x; Bs[kq * 4 + 1][r0 + 64] = b1.y;
        Bs[kq * 4 + 2][r0 + 64] = b1.z; Bs[kq * 4 + 3][r0 + 64] = b1.w;

        __syncthreads();

#pragma unroll
        for (int kk = 0; kk < TBK; kk++) {
            float a[8], bq[8];
            *(float4*)&a[0]  = *(const float4*)&As[kk][ty * 8];
            *(float4*)&a[4]  = *(const float4*)&As[kk][ty * 8 + 4];
            *(float4*)&bq[0] = *(const float4*)&Bs[kk][tx * 8];
            *(float4*)&bq[4] = *(const float4*)&Bs[kk][tx * 8 + 4];
#pragma unroll
            for (int i = 0; i < 8; i++)
#pragma unroll
                for (int j = 0; j < 8; j++)
                    acc[i][j] = fmaf(a[i], bq[j], acc[i][j]);
        }
        __syncthreads();
    }

    // Epilogue: all 8 cols of a thread land in one segment (boundaries at mult. of 64)
    const int c0 = n0 + tx * 8;
    if (c0 < 512) {
#pragma unroll
        for (int i = 0; i < 8; i++) {
            int r = m0 + ty * 8 + i;
            float* base = g_k + (size_t)r * DD + c0;
            *(float4*)(base)     = make_float4(acc[i][0], acc[i][1], acc[i][2], acc[i][3]);
            *(float4*)(base + 4) = make_float4(acc[i][4], acc[i][5], acc[i][6], acc[i][7]);
        }
    } else if (c0 < 1024) {
#pragma unroll
        for (int i = 0; i < 8; i++) {
            int r = m0 + ty * 8 + i;
            float* base = g_q + (size_t)r * DD + (c0 - 512);
            *(float4*)(base)     = make_float4(acc[i][0], acc[i][1], acc[i][2], acc[i][3]);
            *(float4*)(base + 4) = make_float4(acc[i][4], acc[i][5], acc[i][6], acc[i][7]);
        }
    } else if (c0 < 1088) {
        const int cc = c0 - 1024;
        float bb[8];
#pragma unroll
        for (int j = 0; j < 8; j++) bb[j] = bvec[cc + j];
#pragma unroll
        for (int i = 0; i < 8; i++) {
            int r = m0 + ty * 8 + i;
            float* base = g_wx + (size_t)r * NN + cc;
#pragma unroll
            for (int j = 0; j < 8; j++) base[j] = acc[i][j] + bb[j];
        }
    } else {
        const int cc = c0 - 1088;
        float bb[8];
#pragma unroll
        for (int j = 0; j < 8; j++) bb[j] = ba[cc + j];
#pragma unroll
        for (int i = 0; i < 8; i++) {
            int r = m0 + ty * 8 + i;
            float* base = g_alpha + (size_t)r * NN + cc;
#pragma unroll
            for (int j = 0; j < 8; j++)
                base[j] = 1.0f / (1.0f + expf(-(acc[i][j] + bb[j])));
        }
    }
}

// ============================================================================
// Kernel 2: serial recurrence. One cluster of 8 CTAs per batch (N split 8-way).
// CTA rank owns n in [rank*8, rank*8+8); warp w <-> n = rank*8+w; lane owns
// d in [lane*16, lane*16+16) (full D covered by one warp -> Sk & y reductions
// are warp-local). Per step, the 64-float r = tanh(S k) vector is exchanged
// across the cluster via own-SMEM stores + one barrier.cluster + DSMEM loads.
// ============================================================================
__device__ __forceinline__ float warp_sum(float v) {
    v += __shfl_xor_sync(0xffffffffu, v, 16);
    v += __shfl_xor_sync(0xffffffffu, v, 8);
    v += __shfl_xor_sync(0xffffffffu, v, 4);
    v += __shfl_xor_sync(0xffffffffu, v, 2);
    v += __shfl_xor_sync(0xffffffffu, v, 1);
    return v;
}
__device__ __forceinline__ float dot4(const float4 a, const float4 b) {
    return fmaf(a.x, b.x, fmaf(a.y, b.y, fmaf(a.z, b.z, a.w * b.w)));
}
#define UPD4(s, k) do { \
    s.x = fmaf(al, s.x, c2 * k.x); \
    s.y = fmaf(al, s.y, c2 * k.y); \
    s.z = fmaf(al, s.z, c2 * k.z); \
    s.w = fmaf(al, s.w, c2 * k.w); } while (0)

__global__ void __cluster_dims__(8, 1, 1) __launch_bounds__(256, 1)
recur_kernel(const float* __restrict__ S0, const float* __restrict__ Wr,
             float* __restrict__ out)
{
    const int b    = blockIdx.x >> 3;
    const int rank = blockIdx.x & 7;
    const int w    = threadIdx.x >> 5;
    const int lane = threadIdx.x & 31;
    const int n    = rank * 8 + w;

    __shared__ float rbuf[2][8];   // double-buffered r values, one per local warp

    float* out_y = out;                            // [T,B,N]
    float* out_S = out + (size_t)TT * BB * NN;     // [T+1,B,N,D]

    // W_r row fragment: lane holds W_r[n][2*lane], W_r[n][2*lane+1]
    const float2 wrf = *(const float2*)(Wr + n * NN + 2 * lane);

    // Load S0 slice into registers, emit S[0]
    float4 s0_, s1_, s2_, s3_;
    {
        const float4* p = (const float4*)(S0 + (size_t)(b * NN + n) * DD + lane * 16);
        s0_ = p[0]; s1_ = p[1]; s2_ = p[2]; s3_ = p[3];
        float4* sp0 = (float4*)(out_S + (size_t)(b * NN + n) * DD + lane * 16);
        sp0[0] = s0_; sp0[1] = s1_; sp0[2] = s2_; sp0[3] = s3_;
    }

    // DSMEM address for the two r values this lane consumes (m=2*lane, 2*lane+1)
    uint32_t rb_u32;
    {
        void* pp = (void*)&rbuf[0][0];
        asm volatile("{ .reg .u64 t; cvta.to.shared.u64 t, %1; cvt.u32.u64 %0, t; }"
                     : "=r"(rb_u32) : "l"(pp));
    }
    uint32_t remote_base;
    {
        int owner = lane >> 2;   // CTA rank owning m = 2*lane
        asm volatile("mapa.shared::cluster.u32 %0, %1, %2;"
                     : "=r"(remote_base) : "r"(rb_u32), "r"(owner));
    }
    const uint32_t raddr = remote_base + ((2 * lane) & 7) * 4;

    const float* kp  = g_k + b * DD + lane * 16;
    const float* qp  = g_q + b * DD + lane * 16;
    const float* wxp = g_wx + b * NN + n;
    const float* alp = g_alpha + b * NN + n;
    float* yp = out_y + b * NN + n;
    float* sp = out_S + (size_t)((BB + b) * NN + n) * DD + lane * 16;  // S[1] slice

    // Prime t=0 operands
    float4 k0 = *(const float4*)(kp);      float4 k1 = *(const float4*)(kp + 4);
    float4 k2 = *(const float4*)(kp + 8);  float4 k3 = *(const float4*)(kp + 12);
    float4 q0 = *(const float4*)(qp);      float4 q1 = *(const float4*)(qp + 4);
    float4 q2 = *(const float4*)(qp + 8);  float4 q3 = *(const float4*)(qp + 12);
    float wxv = __ldg(wxp);
    float alv = __ldg(alp);

    for (int t = 0; t < TT; t++) {
        // read: r = tanh(S_{t-1} k_t)  (warp-local reduce over full D)
        float sk = dot4(s0_, k0) + dot4(s1_, k1) + dot4(s2_, k2) + dot4(s3_, k3);
        sk = warp_sum(sk);
        float rv = tanhf(sk);
        if (lane == 0) rbuf[t & 1][w] = rv;

        asm volatile("barrier.cluster.arrive.aligned;" ::: "memory");

        // Prefetch next-step operands inside the barrier gap (off critical path)
        const int adv  = (t < TT - 1) ? BB * DD : 0;
        const int advn = (t < TT - 1) ? BB * NN : 0;
        float4 nk0 = *(const float4*)(kp + adv);      float4 nk1 = *(const float4*)(kp + adv + 4);
        float4 nk2 = *(const float4*)(kp + adv + 8);  float4 nk3 = *(const float4*)(kp + adv + 12);
        float4 nq0 = *(const float4*)(qp + adv);      float4 nq1 = *(const float4*)(qp + adv + 4);
        float4 nq2 = *(const float4*)(qp + adv + 8);  float4 nq3 = *(const float4*)(qp + adv + 12);
        float nwx = __ldg(wxp + advn);
        float nal = __ldg(alp + advn);

        asm volatile("barrier.cluster.wait.aligned;" ::: "memory");

        // gather r[m] cluster-wide, v = tanh(W_r r + wx + b)
        float rm0, rm1;
        uint32_t a0 = raddr + ((t & 1) << 5);
        asm volatile("ld.shared::cluster.f32 %0, [%1];" : "=f"(rm0) : "r"(a0));
        asm volatile("ld.shared::cluster.f32 %0, [%1];" : "=f"(rm1) : "r"(a0 + 4));
        float pv = warp_sum(fmaf(wrf.x, rm0, wrf.y * rm1));
        float v  = tanhf(pv + wxv);

        // gated outer-product write
        const float al = alv;
        const float c2 = (1.0f - al) * v;
        UPD4(s0_, k0); UPD4(s1_, k1); UPD4(s2_, k2); UPD4(s3_, k3);

        // stream S_{t+1} to gmem (coalesced: warp covers one full 2KB row)
        {
            float4* so = (float4*)sp;
            so[0] = s0_; so[1] = s1_; so[2] = s2_; so[3] = s3_;
        }

        // y_t = tanh(S_{t+1} q_t)
        float y = dot4(s0_, q0) + dot4(s1_, q1) + dot4(s2_, q2) + dot4(s3_, q3);
        y = warp_sum(y);
        if (lane == 0) *yp = tanhf(y);

        // rotate prefetched operands
        k0 = nk0; k1 = nk1; k2 = nk2; k3 = nk3;
        q0 = nq0; q1 = nq1; q2 = nq2; q3 = nq3;
        wxv = nwx; alv = nal;
        kp += BB * DD; qp += BB * DD; wxp += BB * NN; alp += BB * NN;
        yp += BB * NN; sp += (size_t)BB * NN * DD;
    }
}

// ============================================================================
// Launch
//   inputs (metadata order): x, S0, W_k, W_q, W_x, W_r, b, W_alpha, b_alpha
//   output: concat( y[T,B,N], S[T+1,B,N,D] )  fp32
// ============================================================================
extern "C" void kernel_launch(void* const* d_in, const int* in_sizes, int n_in,
                              void* d_out, int out_size)
{
    const float* x   = (const float*)d_in[0];
    const float* S0  = (const float*)d_in[1];
    const float* Wk  = (const float*)d_in[2];
    const float* Wq  = (const float*)d_in[3];
    const float* Wx  = (const float*)d_in[4];
    const float* Wr  = (const float*)d_in[5];
    const float* bv  = (const float*)d_in[6];
    const float* Wa  = (const float*)d_in[7];
    const float* ba  = (const float*)d_in[8];
    float* out = (float*)d_out;

    dim3 pg(PM / TBM, PN / TBN);   // (32, 9)
    proj_kernel<<<pg, 256>>>(x, Wk, Wq, Wx, Wa, bv, ba);

    recur_kernel<<<64, 256>>>(S0, Wr, out);   // 8 clusters x 8 CTAs (cluster dims compiled in)
}

// round 10
// speedup vs baseline: 1.3805x; 1.3805x over previous
#include <cuda_runtime.h>
#include <cstdint>
#include <math.h>

// Problem constants
#define TT 512
#define BB 8
#define DD 512
#define NN 64

// Scratch (allocation-free rule: __device__ globals)
__device__ float g_k[TT * BB * DD];
__device__ float g_q[TT * BB * DD];
__device__ float g_wx[TT * BB * NN];     // W_x @ x + b  (bias folded)
__device__ float g_alpha[TT * BB * NN];  // sigmoid(W_alpha @ x + b_alpha)

// ---------------------------------------------------------------------------
// Fast tanh: tanh(x) = 1 - 2/(1 + e^{2x})  (MUFU ex2 + rcp; abs err ~1e-7)
// ---------------------------------------------------------------------------
__device__ __forceinline__ float fast_tanh(float x) {
    float e;
    asm("ex2.approx.f32 %0, %1;" : "=f"(e) : "f"(x * 2.8853900817779268f)); // 2*log2(e)*x
    float r;
    asm("rcp.approx.f32 %0, %1;" : "=f"(r) : "f"(e + 1.0f));
    return fmaf(-2.0f, r, 1.0f);
}

// ============================================================================
// Kernel 1: fused projection GEMM (unchanged from R8 — passing, ~100-150us)
//   C[r, j] = sum_d x[r, d] * Wcat[j, d],   r = t*B+b  (M=4096, K=512)
//   cols 0..511 -> k | 512..1023 -> q | 1024..1087 -> wx+b | 1088..1151 -> sigmoid(ax+ba)
// ============================================================================
#define PM 4096
#define PK 512
#define PN 1152
#define TBM 128
#define TBN 128
#define TBK 16

__global__ __launch_bounds__(256) void proj_kernel(
    const float* __restrict__ x,
    const float* __restrict__ Wk, const float* __restrict__ Wq,
    const float* __restrict__ Wx, const float* __restrict__ Wa,
    const float* __restrict__ bvec, const float* __restrict__ ba)
{
    __shared__ float As[TBK][TBM + 4];
    __shared__ float Bs[TBK][TBN + 4];

    const int tid = threadIdx.x;
    const int tx = tid & 15;
    const int ty = tid >> 4;
    const int m0 = blockIdx.x * TBM;
    const int n0 = blockIdx.y * TBN;

    const int kq = tid & 3;
    const int r0 = tid >> 2;

    const float* wr0p;
    const float* wr1p;
    {
        int jg = n0 + r0;
        wr0p = (jg < 512) ? Wk + (size_t)jg * 512
             : (jg < 1024) ? Wq + (size_t)(jg - 512) * 512
             : (jg < 1088) ? Wx + (size_t)(jg - 1024) * 512
                           : Wa + (size_t)(jg - 1088) * 512;
        jg = n0 + r0 + 64;
        wr1p = (jg < 512) ? Wk + (size_t)jg * 512
             : (jg < 1024) ? Wq + (size_t)(jg - 512) * 512
             : (jg < 1088) ? Wx + (size_t)(jg - 1024) * 512
                           : Wa + (size_t)(jg - 1088) * 512;
    }
    const float* xr0 = x + (size_t)(m0 + r0) * PK;
    const float* xr1 = x + (size_t)(m0 + r0 + 64) * PK;

    float acc[8][8];
#pragma unroll
    for (int i = 0; i < 8; i++)
#pragma unroll
        for (int j = 0; j < 8; j++) acc[i][j] = 0.0f;

    for (int kt = 0; kt < PK; kt += TBK) {
        float4 a0 = *(const float4*)(xr0 + kt + kq * 4);
        float4 a1 = *(const float4*)(xr1 + kt + kq * 4);
        float4 b0 = *(const float4*)(wr0p + kt + kq * 4);
        float4 b1 = *(const float4*)(wr1p + kt + kq * 4);

        As[kq * 4 + 0][r0] = a0.x; As[kq * 4 + 1][r0] = a0.y;
        As[kq * 4 + 2][r0] = a0.z; As[kq * 4 + 3][r0] = a0.w;
        As[kq * 4 + 0][r0 + 64] = a1.x; As[kq * 4 + 1][r0 + 64] = a1.y;
        As[kq * 4 + 2][r0 + 64] = a1.z; As[kq * 4 + 3][r0 + 64] = a1.w;

        Bs[kq * 4 + 0][r0] = b0.x; Bs[kq * 4 + 1][r0] = b0.y;
        Bs[kq * 4 + 2][r0] = b0.z; Bs[kq * 4 + 3][r0] = b0.w;
        Bs[kq * 4 + 0][r0 + 64] = b1.x; Bs[kq * 4 + 1][r0 + 64] = b1.y;
        Bs[kq * 4 + 2][r0 + 64] = b1.z; Bs[kq * 4 + 3][r0 + 64] = b1.w;

        __syncthreads();

#pragma unroll
        for (int kk = 0; kk < TBK; kk++) {
            float a[8], bq[8];
            *(float4*)&a[0]  = *(const float4*)&As[kk][ty * 8];
            *(float4*)&a[4]  = *(const float4*)&As[kk][ty * 8 + 4];
            *(float4*)&bq[0] = *(const float4*)&Bs[kk][tx * 8];
            *(float4*)&bq[4] = *(const float4*)&Bs[kk][tx * 8 + 4];
#pragma unroll
            for (int i = 0; i < 8; i++)
#pragma unroll
                for (int j = 0; j < 8; j++)
                    acc[i][j] = fmaf(a[i], bq[j], acc[i][j]);
        }
        __syncthreads();
    }

    const int c0 = n0 + tx * 8;
    if (c0 < 512) {
#pragma unroll
        for (int i = 0; i < 8; i++) {
            int r = m0 + ty * 8 + i;
            float* base = g_k + (size_t)r * DD + c0;
            *(float4*)(base)     = make_float4(acc[i][0], acc[i][1], acc[i][2], acc[i][3]);
            *(float4*)(base + 4) = make_float4(acc[i][4], acc[i][5], acc[i][6], acc[i][7]);
        }
    } else if (c0 < 1024) {
#pragma unroll
        for (int i = 0; i < 8; i++) {
            int r = m0 + ty * 8 + i;
            float* base = g_q + (size_t)r * DD + (c0 - 512);
            *(float4*)(base)     = make_float4(acc[i][0], acc[i][1], acc[i][2], acc[i][3]);
            *(float4*)(base + 4) = make_float4(acc[i][4], acc[i][5], acc[i][6], acc[i][7]);
        }
    } else if (c0 < 1088) {
        const int cc = c0 - 1024;
        float bb[8];
#pragma unroll
        for (int j = 0; j < 8; j++) bb[j] = bvec[cc + j];
#pragma unroll
        for (int i = 0; i < 8; i++) {
            int r = m0 + ty * 8 + i;
            float* base = g_wx + (size_t)r * NN + cc;
#pragma unroll
            for (int j = 0; j < 8; j++) base[j] = acc[i][j] + bb[j];
        }
    } else {
        const int cc = c0 - 1088;
        float bb[8];
#pragma unroll
        for (int j = 0; j < 8; j++) bb[j] = ba[cc + j];
#pragma unroll
        for (int i = 0; i < 8; i++) {
            int r = m0 + ty * 8 + i;
            float* base = g_alpha + (size_t)r * NN + cc;
#pragma unroll
            for (int j = 0; j < 8; j++)
                base[j] = 1.0f / (1.0f + expf(-(acc[i][j] + bb[j])));
        }
    }
}

// ============================================================================
// Kernel 2: serial recurrence, 8-CTA cluster per batch, push-based r exchange.
// Warp w of CTA rank owns row n = rank*8+w; lane owns d in [16*lane, 16*lane+16).
// Per step: warp reduces sk, lanes 0-7 st.async the r value into ALL 8 CTAs'
// local rbuf (+complete_tx on each CTA's mbar). Each CTA arms its mbar with
// expect_tx=256B; consumers do a local acquire try_wait + local LDS.
// ============================================================================
__device__ __forceinline__ float warp_sum(float v) {
    v += __shfl_xor_sync(0xffffffffu, v, 16);
    v += __shfl_xor_sync(0xffffffffu, v, 8);
    v += __shfl_xor_sync(0xffffffffu, v, 4);
    v += __shfl_xor_sync(0xffffffffu, v, 2);
    v += __shfl_xor_sync(0xffffffffu, v, 1);
    return v;
}
__device__ __forceinline__ float dot4(const float4 a, const float4 b) {
    return fmaf(a.x, b.x, fmaf(a.y, b.y, fmaf(a.z, b.z, a.w * b.w)));
}
__device__ __forceinline__ void mbar_wait_cluster(uint32_t mbar, uint32_t parity) {
    asm volatile(
        "{\n\t"
        ".reg .pred P;\n\t"
        "WAIT_%=:\n\t"
        "mbarrier.try_wait.parity.acquire.cluster.shared::cta.b64 P, [%0], %1;\n\t"
        "@!P bra WAIT_%=;\n\t"
        "}" :: "r"(mbar), "r"(parity) : "memory");
}
#define UPD4(s, k) do { \
    s.x = fmaf(al, s.x, c2 * k.x); \
    s.y = fmaf(al, s.y, c2 * k.y); \
    s.z = fmaf(al, s.z, c2 * k.z); \
    s.w = fmaf(al, s.w, c2 * k.w); } while (0)

__global__ void __cluster_dims__(8, 1, 1) __launch_bounds__(256, 1)
recur_kernel(const float* __restrict__ S0, const float* __restrict__ Wr,
             float* __restrict__ out)
{
    const int b    = blockIdx.x >> 3;
    const int rank = blockIdx.x & 7;
    const int w    = threadIdx.x >> 5;
    const int lane = threadIdx.x & 31;
    const int n    = rank * 8 + w;

    __shared__ float rbuf[2][NN];                 // all 64 r values, double-buffered
    __shared__ __align__(8) uint64_t mbar[2];

    const uint32_t rb_local = (uint32_t)__cvta_generic_to_shared(&rbuf[0][0]);
    const uint32_t mb_local = (uint32_t)__cvta_generic_to_shared(&mbar[0]);

    if (threadIdx.x == 0) {
        asm volatile("mbarrier.init.shared.b64 [%0], 1;" :: "r"(mb_local)     : "memory");
        asm volatile("mbarrier.init.shared.b64 [%0], 1;" :: "r"(mb_local + 8) : "memory");
    }
    __syncthreads();
    asm volatile("barrier.cluster.arrive.aligned;" ::: "memory");
    asm volatile("barrier.cluster.wait.aligned;"   ::: "memory");

    // Remote push addresses (lanes 0-7 push to CTA rank = lane)
    uint32_t rb_rem, mb_rem;
    {
        int tgt = lane & 7;
        asm("mapa.shared::cluster.u32 %0, %1, %2;" : "=r"(rb_rem) : "r"(rb_local), "r"(tgt));
        asm("mapa.shared::cluster.u32 %0, %1, %2;" : "=r"(mb_rem) : "r"(mb_local), "r"(tgt));
    }
    const uint32_t push0 = rb_rem + n * 4;   // rbuf[0][n] in target CTA

    float* out_y = out;                            // [T,B,N]
    float* out_S = out + (size_t)TT * BB * NN;     // [T+1,B,N,D]

    // W_r row fragment: lane holds W_r[n][2*lane], W_r[n][2*lane+1]
    const float2 wrf = *(const float2*)(Wr + n * NN + 2 * lane);

    // Load S0 slice into registers, emit S[0]
    float4 s0_, s1_, s2_, s3_;
    {
        const float4* p = (const float4*)(S0 + (size_t)(b * NN + n) * DD + lane * 16);
        s0_ = p[0]; s1_ = p[1]; s2_ = p[2]; s3_ = p[3];
        float4* sp0 = (float4*)(out_S + (size_t)(b * NN + n) * DD + lane * 16);
        sp0[0] = s0_; sp0[1] = s1_; sp0[2] = s2_; sp0[3] = s3_;
    }

    const float* kp  = g_k + b * DD + lane * 16;
    const float* qp  = g_q + b * DD + lane * 16;
    const float* wxp = g_wx + b * NN + n;
    const float* alp = g_alpha + b * NN + n;
    float* yp = out_y + b * NN + n;
    float* sp = out_S + (size_t)((BB + b) * NN + n) * DD + lane * 16;  // S[1] slice

    // Prime t=0 operands
    float4 k0 = *(const float4*)(kp);      float4 k1 = *(const float4*)(kp + 4);
    float4 k2 = *(const float4*)(kp + 8);  float4 k3 = *(const float4*)(kp + 12);
    float4 q0 = *(const float4*)(qp);      float4 q1 = *(const float4*)(qp + 4);
    float4 q2 = *(const float4*)(qp + 8);  float4 q3 = *(const float4*)(qp + 12);
    float wxv = __ldg(wxp);
    float alv = __ldg(alp);

    for (int t = 0; t < TT; t++) {
        const int ib = t & 1;
        const uint32_t par = (t >> 1) & 1;
        const uint32_t mloc = mb_local + ib * 8;

        // Arm this step's barrier: 1 arrival + 256B of incoming st.async data.
        // Safe: this thread passed the wait on mbar[ib] at step t-2, so the
        // previous phase of this mbar is complete before re-arming.
        if (threadIdx.x == 0) {
            asm volatile("mbarrier.arrive.expect_tx.shared.b64 _, [%0], 256;"
                         :: "r"(mloc) : "memory");
        }

        // read: r = tanh(S_{t-1} k_t)  (warp-local reduce over full D)
        float sk = dot4(s0_, k0) + dot4(s1_, k1) + dot4(s2_, k2) + dot4(s3_, k3);
        sk = warp_sum(sk);
        float rv = fast_tanh(sk);

        // push r[n] into every CTA's local rbuf[ib][n] + complete_tx
        if (lane < 8) {
            asm volatile(
                "st.async.shared::cluster.mbarrier::complete_tx::bytes.b32 [%0], %1, [%2];"
                :: "r"(push0 + (uint32_t)(ib * (NN * 4))),
                   "r"(__float_as_uint(rv)),
                   "r"(mb_rem + (uint32_t)(ib * 8))
                : "memory");
        }

        // Prefetch next-step operands inside the exchange gap (off critical path)
        const int adv  = (t < TT - 1) ? BB * DD : 0;
        const int advn = (t < TT - 1) ? BB * NN : 0;
        float4 nk0 = *(const float4*)(kp + adv);      float4 nk1 = *(const float4*)(kp + adv + 4);
        float4 nk2 = *(const float4*)(kp + adv + 8);  float4 nk3 = *(const float4*)(kp + adv + 12);
        float4 nq0 = *(const float4*)(qp + adv);      float4 nq1 = *(const float4*)(qp + adv + 4);
        float4 nq2 = *(const float4*)(qp + adv + 8);  float4 nq3 = *(const float4*)(qp + adv + 12);
        float nwx = __ldg(wxp + advn);
        float nal = __ldg(alp + advn);

        // wait for all 64 r values (local mbar, acquire)
        mbar_wait_cluster(mloc, par);

        // v = tanh(W_r r + wx + b): lane handles m = 2*lane, 2*lane+1 (local LDS)
        float2 rm = *(const float2*)&rbuf[ib][2 * lane];
        float pv = warp_sum(fmaf(wrf.x, rm.x, wrf.y * rm.y));
        float v  = fast_tanh(pv + wxv);

        // gated outer-product write
        const float al = alv;
        const float c2 = (1.0f - al) * v;
        UPD4(s0_, k0); UPD4(s1_, k1); UPD4(s2_, k2); UPD4(s3_, k3);

        // stream S_{t+1} to gmem (coalesced, streaming hint — never re-read)
        __stcs((float4*)sp + 0, s0_);
        __stcs((float4*)sp + 1, s1_);
        __stcs((float4*)sp + 2, s2_);
        __stcs((float4*)sp + 3, s3_);

        // y_t = tanh(S_{t+1} q_t)
        float y = dot4(s0_, q0) + dot4(s1_, q1) + dot4(s2_, q2) + dot4(s3_, q3);
        y = warp_sum(y);
        if (lane == 0) *yp = fast_tanh(y);

        // rotate prefetched operands
        k0 = nk0; k1 = nk1; k2 = nk2; k3 = nk3;
        q0 = nq0; q1 = nq1; q2 = nq2; q3 = nq3;
        wxv = nwx; alv = nal;
        kp += BB * DD; qp += BB * DD; wxp += BB * NN; alp += BB * NN;
        yp += BB * NN; sp += (size_t)BB * NN * DD;
    }
}

// ============================================================================
// Launch
//   inputs (metadata order): x, S0, W_k, W_q, W_x, W_r, b, W_alpha, b_alpha
//   output: concat( y[T,B,N], S[T+1,B,N,D] )  fp32
// ============================================================================
extern "C" void kernel_launch(void* const* d_in, const int* in_sizes, int n_in,
                              void* d_out, int out_size)
{
    const float* x   = (const float*)d_in[0];
    const float* S0  = (const float*)d_in[1];
    const float* Wk  = (const float*)d_in[2];
    const float* Wq  = (const float*)d_in[3];
    const float* Wx  = (const float*)d_in[4];
    const float* Wr  = (const float*)d_in[5];
    const float* bv  = (const float*)d_in[6];
    const float* Wa  = (const float*)d_in[7];
    const float* ba  = (const float*)d_in[8];
    float* out = (float*)d_out;

    dim3 pg(PM / TBM, PN / TBN);   // (32, 9)
    proj_kernel<<<pg, 256>>>(x, Wk, Wq, Wx, Wa, bv, ba);

    recur_kernel<<<64, 256>>>(S0, Wr, out);   // 8 clusters x 8 CTAs
}

// round 11
// speedup vs baseline: 1.3848x; 1.0031x over previous
#include <cuda_runtime.h>
#include <cstdint>
#include <math.h>

// Problem constants
#define TT 512
#define BB 8
#define DD 512
#define NN 64

// Scratch (allocation-free rule: __device__ globals)
__device__ float g_k[TT * BB * DD];
__device__ float g_q[TT * BB * DD];
__device__ float g_wx[TT * BB * NN];     // W_x @ x + b  (bias folded)
__device__ float g_alpha[TT * BB * NN];  // sigmoid(W_alpha @ x + b_alpha)

// ---------------------------------------------------------------------------
// Fast tanh: tanh(x) = 1 - 2/(1 + e^{2x})  (MUFU ex2 + rcp; abs err ~1e-7)
// ---------------------------------------------------------------------------
__device__ __forceinline__ float fast_tanh(float x) {
    float e;
    asm("ex2.approx.f32 %0, %1;" : "=f"(e) : "f"(x * 2.8853900817779268f)); // 2*log2(e)*x
    float r;
    asm("rcp.approx.f32 %0, %1;" : "=f"(r) : "f"(e + 1.0f));
    return fmaf(-2.0f, r, 1.0f);
}

// ============================================================================
// Kernel 1: fused projection GEMM (unchanged — passing, ~50us)
//   cols 0..511 -> k | 512..1023 -> q | 1024..1087 -> wx+b | 1088..1151 -> sigmoid(ax+ba)
// ============================================================================
#define PM 4096
#define PK 512
#define PN 1152
#define TBM 128
#define TBN 128
#define TBK 16

__global__ __launch_bounds__(256) void proj_kernel(
    const float* __restrict__ x,
    const float* __restrict__ Wk, const float* __restrict__ Wq,
    const float* __restrict__ Wx, const float* __restrict__ Wa,
    const float* __restrict__ bvec, const float* __restrict__ ba)
{
    __shared__ float As[TBK][TBM + 4];
    __shared__ float Bs[TBK][TBN + 4];

    const int tid = threadIdx.x;
    const int tx = tid & 15;
    const int ty = tid >> 4;
    const int m0 = blockIdx.x * TBM;
    const int n0 = blockIdx.y * TBN;

    const int kq = tid & 3;
    const int r0 = tid >> 2;

    const float* wr0p;
    const float* wr1p;
    {
        int jg = n0 + r0;
        wr0p = (jg < 512) ? Wk + (size_t)jg * 512
             : (jg < 1024) ? Wq + (size_t)(jg - 512) * 512
             : (jg < 1088) ? Wx + (size_t)(jg - 1024) * 512
                           : Wa + (size_t)(jg - 1088) * 512;
        jg = n0 + r0 + 64;
        wr1p = (jg < 512) ? Wk + (size_t)jg * 512
             : (jg < 1024) ? Wq + (size_t)(jg - 512) * 512
             : (jg < 1088) ? Wx + (size_t)(jg - 1024) * 512
                           : Wa + (size_t)(jg - 1088) * 512;
    }
    const float* xr0 = x + (size_t)(m0 + r0) * PK;
    const float* xr1 = x + (size_t)(m0 + r0 + 64) * PK;

    float acc[8][8];
#pragma unroll
    for (int i = 0; i < 8; i++)
#pragma unroll
        for (int j = 0; j < 8; j++) acc[i][j] = 0.0f;

    for (int kt = 0; kt < PK; kt += TBK) {
        float4 a0 = *(const float4*)(xr0 + kt + kq * 4);
        float4 a1 = *(const float4*)(xr1 + kt + kq * 4);
        float4 b0 = *(const float4*)(wr0p + kt + kq * 4);
        float4 b1 = *(const float4*)(wr1p + kt + kq * 4);

        As[kq * 4 + 0][r0] = a0.x; As[kq * 4 + 1][r0] = a0.y;
        As[kq * 4 + 2][r0] = a0.z; As[kq * 4 + 3][r0] = a0.w;
        As[kq * 4 + 0][r0 + 64] = a1.x; As[kq * 4 + 1][r0 + 64] = a1.y;
        As[kq * 4 + 2][r0 + 64] = a1.z; As[kq * 4 + 3][r0 + 64] = a1.w;

        Bs[kq * 4 + 0][r0] = b0.x; Bs[kq * 4 + 1][r0] = b0.y;
        Bs[kq * 4 + 2][r0] = b0.z; Bs[kq * 4 + 3][r0] = b0.w;
        Bs[kq * 4 + 0][r0 + 64] = b1.x; Bs[kq * 4 + 1][r0 + 64] = b1.y;
        Bs[kq * 4 + 2][r0 + 64] = b1.z; Bs[kq * 4 + 3][r0 + 64] = b1.w;

        __syncthreads();

#pragma unroll
        for (int kk = 0; kk < TBK; kk++) {
            float a[8], bq[8];
            *(float4*)&a[0]  = *(const float4*)&As[kk][ty * 8];
            *(float4*)&a[4]  = *(const float4*)&As[kk][ty * 8 + 4];
            *(float4*)&bq[0] = *(const float4*)&Bs[kk][tx * 8];
            *(float4*)&bq[4] = *(const float4*)&Bs[kk][tx * 8 + 4];
#pragma unroll
            for (int i = 0; i < 8; i++)
#pragma unroll
                for (int j = 0; j < 8; j++)
                    acc[i][j] = fmaf(a[i], bq[j], acc[i][j]);
        }
        __syncthreads();
    }

    const int c0 = n0 + tx * 8;
    if (c0 < 512) {
#pragma unroll
        for (int i = 0; i < 8; i++) {
            int r = m0 + ty * 8 + i;
            float* base = g_k + (size_t)r * DD + c0;
            *(float4*)(base)     = make_float4(acc[i][0], acc[i][1], acc[i][2], acc[i][3]);
            *(float4*)(base + 4) = make_float4(acc[i][4], acc[i][5], acc[i][6], acc[i][7]);
        }
    } else if (c0 < 1024) {
#pragma unroll
        for (int i = 0; i < 8; i++) {
            int r = m0 + ty * 8 + i;
            float* base = g_q + (size_t)r * DD + (c0 - 512);
            *(float4*)(base)     = make_float4(acc[i][0], acc[i][1], acc[i][2], acc[i][3]);
            *(float4*)(base + 4) = make_float4(acc[i][4], acc[i][5], acc[i][6], acc[i][7]);
        }
    } else if (c0 < 1088) {
        const int cc = c0 - 1024;
        float bb[8];
#pragma unroll
        for (int j = 0; j < 8; j++) bb[j] = bvec[cc + j];
#pragma unroll
        for (int i = 0; i < 8; i++) {
            int r = m0 + ty * 8 + i;
            float* base = g_wx + (size_t)r * NN + cc;
#pragma unroll
            for (int j = 0; j < 8; j++) base[j] = acc[i][j] + bb[j];
        }
    } else {
        const int cc = c0 - 1088;
        float bb[8];
#pragma unroll
        for (int j = 0; j < 8; j++) bb[j] = ba[cc + j];
#pragma unroll
        for (int i = 0; i < 8; i++) {
            int r = m0 + ty * 8 + i;
            float* base = g_alpha + (size_t)r * NN + cc;
#pragma unroll
            for (int j = 0; j < 8; j++)
                base[j] = 1.0f / (1.0f + expf(-(acc[i][j] + bb[j])));
        }
    }
}

// ============================================================================
// Kernel 2: serial recurrence, 8-CTA cluster per batch.
// Exchange redesign: local gather of the 8 per-warp r values into rstage,
// then warp0 lanes 0-7 cp.async.bulk 32B blocks to every CTA's rbuf (8
// complete_tx arrivals per mbar instead of 64 st.async arrivals).
// Telescoped recurrence: S_t.k_{t+1} = al*(S_{t-1}.k_{t+1}) + c2*(k_t.k_{t+1})
// lets all 4 big dot products run inside the exchange-wait gap.
// ============================================================================
__device__ __forceinline__ float warp_sum(float v) {
    v += __shfl_xor_sync(0xffffffffu, v, 16);
    v += __shfl_xor_sync(0xffffffffu, v, 8);
    v += __shfl_xor_sync(0xffffffffu, v, 4);
    v += __shfl_xor_sync(0xffffffffu, v, 2);
    v += __shfl_xor_sync(0xffffffffu, v, 1);
    return v;
}
__device__ __forceinline__ float dot4(const float4 a, const float4 b) {
    return fmaf(a.x, b.x, fmaf(a.y, b.y, fmaf(a.z, b.z, a.w * b.w)));
}
__device__ __forceinline__ void mbar_wait_cluster(uint32_t mbar, uint32_t parity) {
    asm volatile(
        "{\n\t"
        ".reg .pred P;\n\t"
        "WAIT_%=:\n\t"
        "mbarrier.try_wait.parity.acquire.cluster.shared::cta.b64 P, [%0], %1;\n\t"
        "@!P bra WAIT_%=;\n\t"
        "}" :: "r"(mbar), "r"(parity) : "memory");
}
#define UPD4(s, k) do { \
    s.x = fmaf(al, s.x, c2 * k.x); \
    s.y = fmaf(al, s.y, c2 * k.y); \
    s.z = fmaf(al, s.z, c2 * k.z); \
    s.w = fmaf(al, s.w, c2 * k.w); } while (0)

__global__ void __cluster_dims__(8, 1, 1) __launch_bounds__(256, 1)
recur_kernel(const float* __restrict__ S0, const float* __restrict__ Wr,
             float* __restrict__ out)
{
    const int b    = blockIdx.x >> 3;
    const int rank = blockIdx.x & 7;
    const int w    = threadIdx.x >> 5;
    const int lane = threadIdx.x & 31;
    const int n    = rank * 8 + w;

    __shared__ __align__(16) float rstage[2][8];   // local 8 r values (32B block)
    __shared__ __align__(16) float rbuf[2][NN];    // gathered 64 r values
    __shared__ __align__(8)  uint64_t mbar[2];

    const uint32_t rs_local = (uint32_t)__cvta_generic_to_shared(&rstage[0][0]);
    const uint32_t rb_local = (uint32_t)__cvta_generic_to_shared(&rbuf[0][0]);
    const uint32_t mb_local = (uint32_t)__cvta_generic_to_shared(&mbar[0]);

    if (threadIdx.x == 0) {
        asm volatile("mbarrier.init.shared.b64 [%0], 1;" :: "r"(mb_local)     : "memory");
        asm volatile("mbarrier.init.shared.b64 [%0], 1;" :: "r"(mb_local + 8) : "memory");
    }
    __syncthreads();
    asm volatile("barrier.cluster.arrive.aligned;" ::: "memory");
    asm volatile("barrier.cluster.wait.aligned;"   ::: "memory");

    // Push targets for warp0 lanes 0-7: CTA rank = lane
    uint32_t dst_rbuf = 0, dst_mbar = 0;
    if (w == 0 && lane < 8) {
        asm("mapa.shared::cluster.u32 %0, %1, %2;" : "=r"(dst_rbuf) : "r"(rb_local), "r"(lane));
        asm("mapa.shared::cluster.u32 %0, %1, %2;" : "=r"(dst_mbar) : "r"(mb_local), "r"(lane));
        dst_rbuf += rank * 32;   // our 8-float block lands at rbuf[ib][rank*8]
    }

    float* out_y = out;                            // [T,B,N]
    float* out_S = out + (size_t)TT * BB * NN;     // [T+1,B,N,D]

    // W_r row fragment: lane holds W_r[n][2*lane], W_r[n][2*lane+1]
    const float2 wrf = *(const float2*)(Wr + n * NN + 2 * lane);

    // Load S0 slice into registers, emit S[0]
    float4 s0_, s1_, s2_, s3_;
    {
        const float4* p = (const float4*)(S0 + (size_t)(b * NN + n) * DD + lane * 16);
        s0_ = p[0]; s1_ = p[1]; s2_ = p[2]; s3_ = p[3];
        float4* sp0 = (float4*)(out_S + (size_t)(b * NN + n) * DD + lane * 16);
        sp0[0] = s0_; sp0[1] = s1_; sp0[2] = s2_; sp0[3] = s3_;
    }

    const float* kp  = g_k + b * DD + lane * 16;       // k_t slice
    const float* qp  = g_q + b * DD + lane * 16;
    const float* wxp = g_wx + b * NN + n;
    const float* alp = g_alpha + b * NN + n;
    float* yp = out_y + b * NN + n;
    float* sp = out_S + (size_t)((BB + b) * NN + n) * DD + lane * 16;  // S[1] slice

    // Prologue: k_0, q_0, wx_0, al_0 current; kn = k_1 prefetch
    float4 k0 = *(const float4*)(kp);      float4 k1 = *(const float4*)(kp + 4);
    float4 k2 = *(const float4*)(kp + 8);  float4 k3 = *(const float4*)(kp + 12);
    float4 q0 = *(const float4*)(qp);      float4 q1 = *(const float4*)(qp + 4);
    float4 q2 = *(const float4*)(qp + 8);  float4 q3 = *(const float4*)(qp + 12);
    float4 kn0 = *(const float4*)(kp + BB * DD);      float4 kn1 = *(const float4*)(kp + BB * DD + 4);
    float4 kn2 = *(const float4*)(kp + BB * DD + 8);  float4 kn3 = *(const float4*)(kp + BB * DD + 12);
    float wxv = __ldg(wxp);
    float alv = __ldg(alp);

    // r_0 = tanh(S0 . k_0)
    float rv;
    {
        float sk = dot4(s0_, k0) + dot4(s1_, k1) + dot4(s2_, k2) + dot4(s3_, k3);
        rv = fast_tanh(warp_sum(sk));
    }

    for (int t = 0; t < TT; t++) {
        const int ib = t & 1;
        const uint32_t par = (t >> 1) & 1;
        const uint32_t mloc = mb_local + ib * 8;

        // Arm: 1 arrival + 8x32B incoming bulk copies. Early complete_tx is
        // fine (tx counter goes negative; phase needs this arrive anyway).
        if (threadIdx.x == 0) {
            asm volatile("mbarrier.arrive.expect_tx.shared.b64 _, [%0], 256;"
                         :: "r"(mloc) : "memory");
        }

        // Gather the 8 local r values, then bulk-push the 32B block to all CTAs
        if (lane == 0) rstage[ib][w] = rv;
        __syncthreads();
        if (w == 0 && lane < 8) {
            asm volatile("fence.proxy.async.shared::cta;" ::: "memory");
            asm volatile(
                "cp.async.bulk.shared::cluster.shared::cta.mbarrier::complete_tx::bytes "
                "[%0], [%1], 32, [%2];"
                :: "r"(dst_rbuf + (uint32_t)(ib * (NN * 4))),
                   "r"(rs_local + (uint32_t)(ib * 32)),
                   "r"(dst_mbar + (uint32_t)(ib * 8))
                : "memory");
        }

        // ---- Gap work (overlaps exchange transit) ----
        // Telescoped dot products against S_{t-1} and k_t:
        float A  = dot4(s0_, kn0) + dot4(s1_, kn1) + dot4(s2_, kn2) + dot4(s3_, kn3); // S.k_{t+1}
        float Bq = dot4(k0, kn0)  + dot4(k1, kn1)  + dot4(k2, kn2)  + dot4(k3, kn3);  // k_t.k_{t+1}
        float C  = dot4(s0_, q0)  + dot4(s1_, q1)  + dot4(s2_, q2)  + dot4(s3_, q3);  // S.q_t
        float Dq = dot4(k0, q0)   + dot4(k1, q1)   + dot4(k2, q2)   + dot4(k3, q3);   // k_t.q_t
        A = warp_sum(A); Bq = warp_sum(Bq); C = warp_sum(C); Dq = warp_sum(Dq);

        // Prefetch t+2 k, t+1 q/wx/alpha
        const int adv2 = (t < TT - 2) ? 2 * BB * DD : (TT - 1 - t) * BB * DD;
        const int advn = (t < TT - 1) ? BB * NN : 0;
        float4 nk0 = *(const float4*)(kp + adv2);      float4 nk1 = *(const float4*)(kp + adv2 + 4);
        float4 nk2 = *(const float4*)(kp + adv2 + 8);  float4 nk3 = *(const float4*)(kp + adv2 + 12);
        const int advq = (t < TT - 1) ? BB * DD : 0;
        float4 nq0 = *(const float4*)(qp + advq);      float4 nq1 = *(const float4*)(qp + advq + 4);
        float4 nq2 = *(const float4*)(qp + advq + 8);  float4 nq3 = *(const float4*)(qp + advq + 12);
        float nwx = __ldg(wxp + advn);
        float nal = __ldg(alp + advn);

        // ---- Wait for all 64 r values ----
        mbar_wait_cluster(mloc, par);

        // v = tanh(W_r r + wx): lane handles m = 2*lane, 2*lane+1
        float2 rm = *(const float2*)&rbuf[ib][2 * lane];
        float pv = warp_sum(fmaf(wrf.x, rm.x, wrf.y * rm.y));
        float v  = fast_tanh(pv + wxv);

        const float al = alv;
        const float c2 = (1.0f - al) * v;

        // Next step's r from telescoped dot (critical path: 2 FMA + tanh)
        rv = fast_tanh(fmaf(al, A, c2 * Bq));

        // y_t (off critical path)
        float yv = fast_tanh(fmaf(al, C, c2 * Dq));
        if (lane == 0) *yp = yv;

        // S_t = al*S + c2*k ; stream to gmem
        UPD4(s0_, k0); UPD4(s1_, k1); UPD4(s2_, k2); UPD4(s3_, k3);
        __stcs((float4*)sp + 0, s0_);
        __stcs((float4*)sp + 1, s1_);
        __stcs((float4*)sp + 2, s2_);
        __stcs((float4*)sp + 3, s3_);

        // rotate operands
        k0 = kn0; k1 = kn1; k2 = kn2; k3 = kn3;
        kn0 = nk0; kn1 = nk1; kn2 = nk2; kn3 = nk3;
        q0 = nq0; q1 = nq1; q2 = nq2; q3 = nq3;
        wxv = nwx; alv = nal;
        kp += BB * DD; qp += BB * DD; wxp += BB * NN; alp += BB * NN;
        yp += BB * NN; sp += (size_t)BB * NN * DD;
    }
}

// ============================================================================
// Launch
//   inputs (metadata order): x, S0, W_k, W_q, W_x, W_r, b, W_alpha, b_alpha
//   output: concat( y[T,B,N], S[T+1,B,N,D] )  fp32
// ============================================================================
extern "C" void kernel_launch(void* const* d_in, const int* in_sizes, int n_in,
                              void* d_out, int out_size)
{
    const float* x   = (const float*)d_in[0];
    const float* S0  = (const float*)d_in[1];
    const float* Wk  = (const float*)d_in[2];
    const float* Wq  = (const float*)d_in[3];
    const float* Wx  = (const float*)d_in[4];
    const float* Wr  = (const float*)d_in[5];
    const float* bv  = (const float*)d_in[6];
    const float* Wa  = (const float*)d_in[7];
    const float* ba  = (const float*)d_in[8];
    float* out = (float*)d_out;

    dim3 pg(PM / TBM, PN / TBN);   // (32, 9)
    proj_kernel<<<pg, 256>>>(x, Wk, Wq, Wx, Wa, bv, ba);

    recur_kernel<<<64, 256>>>(S0, Wr, out);   // 8 clusters x 8 CTAs
}